// round 14
// baseline (speedup 1.0000x reference)
#include <cuda_runtime.h>

// Problem constants
#define Bb 2
#define Hh 16
#define Tt 2048
#define Kk 64
#define Vv 64
#define Cc 64                 // chunk length
#define NCk (Tt/Cc)           // 32 chunks
#define BH (Bb*Hh)            // 32
#define OUT_T_SIZE (BH*Tt*Vv) // floats of 'out' before state_f
#define PAD 72                // smem row stride (conflict-free fragment loads)

// ---------------- scratch (static __device__, no allocation) ----------------
__device__ float g_aC[BH*NCk*Kk];                   // chunk total decay
__device__ float g_dS[(size_t)BH*NCk*Kk*Vv];        // chunk state delta
__device__ float g_Sc[(size_t)BH*NCk*Kk*Vv];        // state at chunk start
__device__ float g_rt[(size_t)BH*Tt*Kk];            // r~ transposed [bh][c][k][t], tf32-rounded

// ---------------- helpers ----------------
__device__ __forceinline__ void cp_async16(void* smem_dst, const void* gmem_src) {
    unsigned sa = (unsigned)__cvta_generic_to_shared(smem_dst);
    asm volatile("cp.async.cg.shared.global [%0], [%1], 16;" :: "r"(sa), "l"(gmem_src));
}
__device__ __forceinline__ void cp_async_wait_all() {
    asm volatile("cp.async.commit_group;");
    asm volatile("cp.async.wait_group 0;");
}
__device__ __forceinline__ unsigned tf32_of(float x) {
    unsigned u;
    asm("cvt.rna.tf32.f32 %0, %1;" : "=r"(u) : "f"(x));
    return u;
}
__device__ __forceinline__ float tf32r(float x) {       // round-to-tf32, keep as float
    return __uint_as_float(tf32_of(x));
}
// D(16x8) += A(16x8,row) * B(8x8,col) ; tf32 inputs, fp32 accumulate
__device__ __forceinline__ void mma16n8k8(float* d,
    unsigned a0, unsigned a1, unsigned a2, unsigned a3,
    unsigned b0, unsigned b1)
{
    asm volatile(
        "mma.sync.aligned.m16n8k8.row.col.f32.tf32.tf32.f32 "
        "{%0,%1,%2,%3}, {%4,%5,%6,%7}, {%8,%9}, {%0,%1,%2,%3};"
        : "+f"(d[0]), "+f"(d[1]), "+f"(d[2]), "+f"(d[3])
        : "r"(a0), "r"(a1), "r"(a2), "r"(a3), "r"(b0), "r"(b1));
}
__device__ __forceinline__ float4 warp_prod_scan4(float4 a) {
    const int lane = threadIdx.x & 31;
    #pragma unroll
    for (int off = 1; off < 32; off <<= 1) {
        float x0 = __shfl_up_sync(0xffffffffu, a.x, off);
        float x1 = __shfl_up_sync(0xffffffffu, a.y, off);
        float x2 = __shfl_up_sync(0xffffffffu, a.z, off);
        float x3 = __shfl_up_sync(0xffffffffu, a.w, off);
        if (lane >= off) { a.x *= x0; a.y *= x1; a.z *= x2; a.w *= x3; }
    }
    return a;
}
__device__ __forceinline__ float4 shfl_up1_or_one4(float4 a) {
    const int lane = threadIdx.x & 31;
    float4 r;
    r.x = __shfl_up_sync(0xffffffffu, a.x, 1);
    r.y = __shfl_up_sync(0xffffffffu, a.y, 1);
    r.z = __shfl_up_sync(0xffffffffu, a.z, 1);
    r.w = __shfl_up_sync(0xffffffffu, a.w, 1);
    if (lane == 0) r = make_float4(1.f, 1.f, 1.f, 1.f);
    return r;
}
__device__ __forceinline__ float4 shfl31_4(float4 a) {
    float4 r;
    r.x = __shfl_sync(0xffffffffu, a.x, 31);
    r.y = __shfl_sync(0xffffffffu, a.y, 31);
    r.z = __shfl_sync(0xffffffffu, a.z, 31);
    r.w = __shfl_sync(0xffffffffu, a.w, 31);
    return r;
}
__device__ __forceinline__ float4 fmax4(float4 a, float e) {
    return make_float4(fmaxf(a.x, e), fmaxf(a.y, e), fmaxf(a.z, e), fmaxf(a.w, e));
}

// ================= kernel A: scan + P + dS + O_intra (3-buffer) =================
// Mid-chunk normalization m = prod(rows 0..31), q_full = prod(rows 32..63).
//  khT[k][t] = k*m/incl;  rhT[k][t] = r~/m;  rt(global) = r~  (tf32-rounded)
//  P[i][j] = sum_k rh[k][i] khT[k][j] (j<i), diag (j==i), 0
//  dS[k][v] = q_full[k] * sum_t khT[k][t] v[t][v] ; O_intra = P.v -> out
// Buffer lifetimes:  A: w -> khT ;  B: r -> rhT -> PT ;  C: k -> v
struct KASmem {
    union { float w[Cc][PAD]; float khT[Kk][PAD]; } A;
    union { float r[Cc][PAD]; float rhT[Kk][PAD]; float PT[Cc][PAD]; } B;
    union { float k[Cc][PAD]; float v[Cc][PAD]; } C;
    float dp[8][66];
    float diag[Cc];
    float sK[Kk];       // q_full per k-column
};

__global__ __launch_bounds__(256, 4) void kA_chunk(
    const float* __restrict__ r, const float* __restrict__ k,
    const float* __restrict__ v, const float* __restrict__ w,
    const float* __restrict__ u, float* __restrict__ out)
{
    extern __shared__ char smem_raw[];
    KASmem& sm = *reinterpret_cast<KASmem*>(smem_raw);

    const int bh = blockIdx.y;
    const int h  = bh & (Hh - 1);
    const int tid  = threadIdx.x;
    const int lane = tid & 31;
    const int wi   = tid >> 5;
    const int g  = lane >> 2;      // mma groupID
    const int tg = lane & 3;       // mma thread-in-group
    const int mw = (wi & 3) * 16;  // warp output row base
    const int nw = (wi >> 2) * 32; // warp output col base

    #pragma unroll 1
    for (int half = 0; half < 2; half++) {
        const int c  = blockIdx.x + half * (NCk / 2);
        const int t0 = c * Cc;

        // ---- stage w, r, k (NOT v) row-major via cp.async ----
        {
            const float4* wp = (const float4*)(w + ((size_t)h  * Tt + t0) * Kk);
            const float4* rp = (const float4*)(r + ((size_t)bh * Tt + t0) * Kk);
            const float4* kp = (const float4*)(k + ((size_t)bh * Tt + t0) * Kk);
            #pragma unroll
            for (int i = tid; i < Cc * Kk / 4; i += 256) {
                int t = i >> 4, k0 = (i & 15) * 4;
                cp_async16(&sm.A.w[t][k0], &wp[i]);
                cp_async16(&sm.B.r[t][k0], &rp[i]);
                cp_async16(&sm.C.k[t][k0], &kp[i]);
            }
            cp_async_wait_all();
        }
        __syncthreads();

        // ---- scan phase: read rows into regs, compute all normalized forms ----
        float4 kh0[2], kh1[2], rh0[2], rh1[2];
        {
            float dA = 0.0f, dB = 0.0f;
            #pragma unroll
            for (int gg = 0; gg < 2; gg++) {
                const int kk4 = wi * 8 + gg * 4;
                float4 w0 = fmax4(*(const float4*)&sm.A.w[lane][kk4],      1e-6f);
                float4 w1 = fmax4(*(const float4*)&sm.A.w[32 + lane][kk4], 1e-6f);
                float4 r0 = *(const float4*)&sm.B.r[lane][kk4];
                float4 r1 = *(const float4*)&sm.B.r[32 + lane][kk4];
                float4 c0 = *(const float4*)&sm.C.k[lane][kk4];
                float4 c1 = *(const float4*)&sm.C.k[32 + lane][kk4];

                float4 p = warp_prod_scan4(w0);     // prod rows 0..lane
                float4 q = warp_prod_scan4(w1);     // prod rows 32..32+lane
                float4 m    = shfl31_4(p);          // prod rows 0..31
                float4 qf   = shfl31_4(q);          // prod rows 32..63
                float4 pre  = shfl_up1_or_one4(p);
                float4 pre2 = shfl_up1_or_one4(q);
                float4 u4 = *(const float4*)&u[h * Kk + kk4];

                dA = fmaf(r0.x * c0.x, u4.x, dA); dA = fmaf(r0.y * c0.y, u4.y, dA);
                dA = fmaf(r0.z * c0.z, u4.z, dA); dA = fmaf(r0.w * c0.w, u4.w, dA);
                dB = fmaf(r1.x * c1.x, u4.x, dB); dB = fmaf(r1.y * c1.y, u4.y, dB);
                dB = fmaf(r1.z * c1.z, u4.z, dB); dB = fmaf(r1.w * c1.w, u4.w, dB);

                // normalized forms (pre-rounded to tf32)
                kh0[gg] = make_float4(tf32r(c0.x * m.x / p.x), tf32r(c0.y * m.y / p.y),
                                      tf32r(c0.z * m.z / p.z), tf32r(c0.w * m.w / p.w));
                kh1[gg] = make_float4(tf32r(c1.x / q.x), tf32r(c1.y / q.y),
                                      tf32r(c1.z / q.z), tf32r(c1.w / q.w));
                rh0[gg] = make_float4(tf32r(r0.x * pre.x / m.x), tf32r(r0.y * pre.y / m.y),
                                      tf32r(r0.z * pre.z / m.z), tf32r(r0.w * pre.w / m.w));
                rh1[gg] = make_float4(tf32r(r1.x * pre2.x), tf32r(r1.y * pre2.y),
                                      tf32r(r1.z * pre2.z), tf32r(r1.w * pre2.w));

                // r~ to global (transposed [k][t], tf32-rounded), coalesced per kk
                {
                    float* rtb = g_rt + ((size_t)(bh * NCk + c)) * Kk * Cc;
                    float rt0v[4] = {tf32r(r0.x * pre.x), tf32r(r0.y * pre.y),
                                     tf32r(r0.z * pre.z), tf32r(r0.w * pre.w)};
                    float rt1v[4] = {tf32r(r1.x * (m.x * pre2.x)), tf32r(r1.y * (m.y * pre2.y)),
                                     tf32r(r1.z * (m.z * pre2.z)), tf32r(r1.w * (m.w * pre2.w))};
                    #pragma unroll
                    for (int cc = 0; cc < 4; cc++) {
                        rtb[(kk4 + cc) * Cc + lane]      = rt0v[cc];
                        rtb[(kk4 + cc) * Cc + 32 + lane] = rt1v[cc];
                    }
                }
                if (lane == 0) {
                    float4 aC;
                    aC.x = m.x * qf.x; aC.y = m.y * qf.y;
                    aC.z = m.z * qf.z; aC.w = m.w * qf.w;
                    *(float4*)&g_aC[(bh * NCk + c) * Kk + kk4] = aC;
                    *(float4*)&sm.sK[kk4] = qf;
                }
            }
            sm.dp[wi][lane]      = dA;
            sm.dp[wi][32 + lane] = dB;
        }
        __syncthreads();   // sync1: all w/r/k reads + dp writes complete

        // ---- overlap: v load into C (k dead) + transposed writes + diag ----
        {
            const float4* vp = (const float4*)(v + ((size_t)bh * Tt + t0) * Vv);
            #pragma unroll
            for (int i = tid; i < Cc * Kk / 4; i += 256) {
                int t = i >> 4, k0 = (i & 15) * 4;
                cp_async16(&sm.C.v[t][k0], &vp[i]);
            }
        }
        #pragma unroll
        for (int gg = 0; gg < 2; gg++) {
            const int kk4 = wi * 8 + gg * 4;
            sm.A.khT[kk4 + 0][lane] = kh0[gg].x; sm.A.khT[kk4 + 1][lane] = kh0[gg].y;
            sm.A.khT[kk4 + 2][lane] = kh0[gg].z; sm.A.khT[kk4 + 3][lane] = kh0[gg].w;
            sm.A.khT[kk4 + 0][32 + lane] = kh1[gg].x; sm.A.khT[kk4 + 1][32 + lane] = kh1[gg].y;
            sm.A.khT[kk4 + 2][32 + lane] = kh1[gg].z; sm.A.khT[kk4 + 3][32 + lane] = kh1[gg].w;
            sm.B.rhT[kk4 + 0][lane] = rh0[gg].x; sm.B.rhT[kk4 + 1][lane] = rh0[gg].y;
            sm.B.rhT[kk4 + 2][lane] = rh0[gg].z; sm.B.rhT[kk4 + 3][lane] = rh0[gg].w;
            sm.B.rhT[kk4 + 0][32 + lane] = rh1[gg].x; sm.B.rhT[kk4 + 1][32 + lane] = rh1[gg].y;
            sm.B.rhT[kk4 + 2][32 + lane] = rh1[gg].z; sm.B.rhT[kk4 + 3][32 + lane] = rh1[gg].w;
        }
        if (tid < Cc) {   // diag from dp (written before sync1)
            float d = 0.0f;
            #pragma unroll
            for (int j = 0; j < 8; j++) d += sm.dp[j][tid];
            sm.diag[tid] = d;
        }
        __syncthreads();   // sync2: khT, rhT, diag visible

        float acc[4][4];

        // ---- P MMA: P[i][j] = sum_k rhT[k][i] khT[k][j]  (no v needed) ----
        #pragma unroll
        for (int nt = 0; nt < 4; nt++)
            #pragma unroll
            for (int q2 = 0; q2 < 4; q2++) acc[nt][q2] = 0.0f;
        #pragma unroll
        for (int ks = 0; ks < 8; ks++) {
            const int kd0 = ks * 8 + tg;
            const int kd1 = kd0 + 4;
            unsigned a0 = __float_as_uint(sm.B.rhT[kd0][mw + g]);
            unsigned a1 = __float_as_uint(sm.B.rhT[kd0][mw + g + 8]);
            unsigned a2 = __float_as_uint(sm.B.rhT[kd1][mw + g]);
            unsigned a3 = __float_as_uint(sm.B.rhT[kd1][mw + g + 8]);
            #pragma unroll
            for (int nt = 0; nt < 4; nt++) {
                unsigned b0 = __float_as_uint(sm.A.khT[kd0][nw + nt * 8 + g]);
                unsigned b1 = __float_as_uint(sm.A.khT[kd1][nw + nt * 8 + g]);
                mma16n8k8(acc[nt], a0, a1, a2, a3, b0, b1);
            }
        }
        float dg0 = sm.diag[mw + g];
        float dg1 = sm.diag[mw + g + 8];

        cp_async_wait_all();   // v arrived (this thread's group)
        __syncthreads();       // sync3: P-MMA rhT reads done; v visible block-wide

        // ---- store masked PT -> B (rhT dead) ----
        #pragma unroll
        for (int nt = 0; nt < 4; nt++) {
            int jb = nw + nt * 8 + 2 * tg;
            int i0 = mw + g, i1 = mw + g + 8;
            sm.B.PT[jb][i0]     = tf32r((jb     < i0) ? acc[nt][0] : ((jb     == i0) ? dg0 : 0.0f));
            sm.B.PT[jb + 1][i0] = tf32r((jb + 1 < i0) ? acc[nt][1] : ((jb + 1 == i0) ? dg0 : 0.0f));
            sm.B.PT[jb][i1]     = tf32r((jb     < i1) ? acc[nt][2] : ((jb     == i1) ? dg1 : 0.0f));
            sm.B.PT[jb + 1][i1] = tf32r((jb + 1 < i1) ? acc[nt][3] : ((jb + 1 == i1) ? dg1 : 0.0f));
        }

        // ---- dS MMA: dS[k][v] = sK[k] * sum_t khT[k][t] v[t][v] ----
        #pragma unroll
        for (int nt = 0; nt < 4; nt++)
            #pragma unroll
            for (int q2 = 0; q2 < 4; q2++) acc[nt][q2] = 0.0f;
        #pragma unroll
        for (int ks = 0; ks < 8; ks++) {
            const int td0 = ks * 8 + tg;
            const int td1 = td0 + 4;
            unsigned a0 = __float_as_uint(sm.A.khT[mw + g][td0]);
            unsigned a1 = __float_as_uint(sm.A.khT[mw + g + 8][td0]);
            unsigned a2 = __float_as_uint(sm.A.khT[mw + g][td1]);
            unsigned a3 = __float_as_uint(sm.A.khT[mw + g + 8][td1]);
            #pragma unroll
            for (int nt = 0; nt < 4; nt++) {
                unsigned b0 = tf32_of(sm.C.v[td0][nw + nt * 8 + g]);
                unsigned b1 = tf32_of(sm.C.v[td1][nw + nt * 8 + g]);
                mma16n8k8(acc[nt], a0, a1, a2, a3, b0, b1);
            }
        }
        {
            float s0 = sm.sK[mw + g], s1 = sm.sK[mw + g + 8];
            float* dsp = g_dS + (size_t)(bh * NCk + c) * Kk * Vv;
            #pragma unroll
            for (int nt = 0; nt < 4; nt++) {
                int col = nw + nt * 8 + 2 * tg;
                *(float2*)&dsp[(size_t)(mw + g)     * Vv + col] =
                    make_float2(acc[nt][0] * s0, acc[nt][1] * s0);
                *(float2*)&dsp[(size_t)(mw + g + 8) * Vv + col] =
                    make_float2(acc[nt][2] * s1, acc[nt][3] * s1);
            }
        }
        __syncthreads();   // sync4: PT visible

        // ---- O_intra MMA: O[t][v] = sum_j PT[j][t] v[j][v]  -> out ----
        #pragma unroll
        for (int nt = 0; nt < 4; nt++)
            #pragma unroll
            for (int q2 = 0; q2 < 4; q2++) acc[nt][q2] = 0.0f;
        #pragma unroll
        for (int ks = 0; ks < 8; ks++) {
            const int jd0 = ks * 8 + tg;
            const int jd1 = jd0 + 4;
            unsigned a0 = __float_as_uint(sm.B.PT[jd0][mw + g]);
            unsigned a1 = __float_as_uint(sm.B.PT[jd0][mw + g + 8]);
            unsigned a2 = __float_as_uint(sm.B.PT[jd1][mw + g]);
            unsigned a3 = __float_as_uint(sm.B.PT[jd1][mw + g + 8]);
            #pragma unroll
            for (int nt = 0; nt < 4; nt++) {
                unsigned b0 = tf32_of(sm.C.v[jd0][nw + nt * 8 + g]);
                unsigned b1 = tf32_of(sm.C.v[jd1][nw + nt * 8 + g]);
                mma16n8k8(acc[nt], a0, a1, a2, a3, b0, b1);
            }
        }
        {
            float* op = out + ((size_t)bh * Tt + t0) * Vv;
            #pragma unroll
            for (int nt = 0; nt < 4; nt++) {
                int col = nw + nt * 8 + 2 * tg;
                *(float2*)&op[(size_t)(mw + g)     * Vv + col] = make_float2(acc[nt][0], acc[nt][1]);
                *(float2*)&op[(size_t)(mw + g + 8) * Vv + col] = make_float2(acc[nt][2], acc[nt][3]);
            }
        }
        __syncthreads();   // before restaging next chunk
    }
}

// ================= kernel 2: sequential chunk-level state scan =================
__global__ __launch_bounds__(256) void k2_scan(
    const float* __restrict__ state_in, float* __restrict__ out)
{
    const int bh  = blockIdx.y;
    const int tid = threadIdx.x;
    const int fi  = blockIdx.x * 256 + tid;
    const int krow = fi >> 4;

    float4 S = ((const float4*)(state_in + (size_t)bh * Kk * Vv))[fi];

    const float*  aCb = g_aC + bh * NCk * Kk;
    const float4* dSb = (const float4*)(g_dS + (size_t)bh * NCk * Kk * Vv);
    float4*       Scb = (float4*)(g_Sc + (size_t)bh * NCk * Kk * Vv);

    float4 db[2][4];
    float  ab[2][4];

    #pragma unroll
    for (int j = 0; j < 4; j++) {
        db[0][j] = dSb[(size_t)j * 1024 + fi];
        ab[0][j] = aCb[j * Kk + krow];
    }

    #pragma unroll 1
    for (int gq = 0; gq < NCk / 4; gq++) {
        const int cur = gq & 1;
        if (gq + 1 < NCk / 4) {
            #pragma unroll
            for (int j = 0; j < 4; j++) {
                int c = (gq + 1) * 4 + j;
                db[cur ^ 1][j] = dSb[(size_t)c * 1024 + fi];
                ab[cur ^ 1][j] = aCb[c * Kk + krow];
            }
        }
        #pragma unroll
        for (int j = 0; j < 4; j++) {
            int c = gq * 4 + j;
            Scb[(size_t)c * 1024 + fi] = S;
            float a = ab[cur][j]; float4 d = db[cur][j];
            S.x = fmaf(a, S.x, d.x); S.y = fmaf(a, S.y, d.y);
            S.z = fmaf(a, S.z, d.z); S.w = fmaf(a, S.w, d.w);
        }
    }

    ((float4*)(out + (size_t)OUT_T_SIZE + (size_t)bh * Kk * Vv))[fi] = S;
}

// ================= kernel B: cross-chunk term, O += rt . S =================
// One chunk per block (grid 1024): 6 blocks/SM of overlap hides staging latency.
struct KBSmem {
    float rtT[Kk][PAD];   // [k][t], tf32-rounded already
    float S[Kk][PAD];     // [k][v], raw fp32 (converted at fragment load)
};

__global__ __launch_bounds__(256, 6) void kB_cross(
    float* __restrict__ out)
{
    extern __shared__ char smem_raw[];
    KBSmem& sm = *reinterpret_cast<KBSmem*>(smem_raw);

    const int c  = blockIdx.x;
    const int bh = blockIdx.y;
    const int t0 = c * Cc;
    const int tid  = threadIdx.x;
    const int lane = tid & 31;
    const int wi   = tid >> 5;
    const int g  = lane >> 2;
    const int tg = lane & 3;
    const int mw = (wi & 3) * 16;
    const int nw = (wi >> 2) * 32;

    // ---- stage rtT + Sc ----
    {
        const float4* rp = (const float4*)(g_rt + ((size_t)(bh * NCk + c)) * Kk * Cc);
        const float4* Sp = (const float4*)(g_Sc + (size_t)(bh * NCk + c) * Kk * Vv);
        #pragma unroll
        for (int i = tid; i < Kk * Cc / 4; i += 256) {
            int row = i >> 4, c4 = (i & 15) * 4;
            cp_async16(&sm.rtT[row][c4], &rp[i]);
            cp_async16(&sm.S[row][c4],   &Sp[i]);
        }
        cp_async_wait_all();
    }
    __syncthreads();

    // ---- O_cross MMA: O[t][v] += sum_k rtT[k][t] S[k][v] ----
    float acc[4][4];
    #pragma unroll
    for (int nt = 0; nt < 4; nt++)
        #pragma unroll
        for (int q2 = 0; q2 < 4; q2++) acc[nt][q2] = 0.0f;

    #pragma unroll
    for (int ks = 0; ks < 8; ks++) {
        const int kd0 = ks * 8 + tg;
        const int kd1 = kd0 + 4;
        unsigned a0 = __float_as_uint(sm.rtT[kd0][mw + g]);
        unsigned a1 = __float_as_uint(sm.rtT[kd0][mw + g + 8]);
        unsigned a2 = __float_as_uint(sm.rtT[kd1][mw + g]);
        unsigned a3 = __float_as_uint(sm.rtT[kd1][mw + g + 8]);
        #pragma unroll
        for (int nt = 0; nt < 4; nt++) {
            unsigned b0 = tf32_of(sm.S[kd0][nw + nt * 8 + g]);
            unsigned b1 = tf32_of(sm.S[kd1][nw + nt * 8 + g]);
            mma16n8k8(acc[nt], a0, a1, a2, a3, b0, b1);
        }
    }

    // ---- read-modify-write out ----
    float* op = out + ((size_t)bh * Tt + t0) * Vv;
    #pragma unroll
    for (int nt = 0; nt < 4; nt++) {
        int col = nw + nt * 8 + 2 * tg;
        float2* p0 = (float2*)&op[(size_t)(mw + g)     * Vv + col];
        float2* p1 = (float2*)&op[(size_t)(mw + g + 8) * Vv + col];
        float2 o0 = *p0, o1 = *p1;
        o0.x += acc[nt][0]; o0.y += acc[nt][1];
        o1.x += acc[nt][2]; o1.y += acc[nt][3];
        *p0 = o0; *p1 = o1;
    }
}

// ---------------- launch ----------------
extern "C" void kernel_launch(void* const* d_in, const int* in_sizes, int n_in,
                              void* d_out, int out_size)
{
    const float* r  = (const float*)d_in[0];
    const float* k  = (const float*)d_in[1];
    const float* v  = (const float*)d_in[2];
    const float* w  = (const float*)d_in[3];
    const float* u  = (const float*)d_in[4];
    const float* st = (const float*)d_in[5];
    float* out = (float*)d_out;

    static bool configured = false;
    if (!configured) {
        cudaFuncSetAttribute(kA_chunk, cudaFuncAttributeMaxDynamicSharedMemorySize,
                             (int)sizeof(KASmem));
        cudaFuncSetAttribute(kB_cross, cudaFuncAttributeMaxDynamicSharedMemorySize,
                             (int)sizeof(KBSmem));
        configured = true;
    }

    kA_chunk<<<dim3(NCk / 2, BH), 256, sizeof(KASmem)>>>(r, k, v, w, u, out);
    k2_scan<<<dim3(4, BH), 256>>>(st, out);
    kB_cross<<<dim3(NCk, BH), 256, sizeof(KBSmem)>>>(out);
}

// round 15
// speedup vs baseline: 1.0327x; 1.0327x over previous
#include <cuda_runtime.h>

// Problem constants
#define Bb 2
#define Hh 16
#define Tt 2048
#define Kk 64
#define Vv 64
#define Cc 64                 // chunk length
#define NCk (Tt/Cc)           // 32 chunks
#define BH (Bb*Hh)            // 32
#define OUT_T_SIZE (BH*Tt*Vv) // floats of 'out' before state_f
#define PAD 72                // smem row stride (conflict-free fragment loads)

// ---------------- scratch (static __device__, no allocation) ----------------
__device__ float g_aC[BH*NCk*Kk];                   // chunk total decay
__device__ float g_dS[(size_t)BH*NCk*Kk*Vv];        // chunk state delta
__device__ float g_Sc[(size_t)BH*NCk*Kk*Vv];        // state at chunk start
__device__ float g_rt[(size_t)BH*Tt*Kk];            // r~ transposed [bh][c][k][t], tf32-rounded

// ---------------- helpers ----------------
__device__ __forceinline__ void cp_async16(void* smem_dst, const void* gmem_src) {
    unsigned sa = (unsigned)__cvta_generic_to_shared(smem_dst);
    asm volatile("cp.async.cg.shared.global [%0], [%1], 16;" :: "r"(sa), "l"(gmem_src));
}
__device__ __forceinline__ void cp_async_wait_all() {
    asm volatile("cp.async.commit_group;");
    asm volatile("cp.async.wait_group 0;");
}
__device__ __forceinline__ unsigned tf32_of(float x) {
    unsigned u;
    asm("cvt.rna.tf32.f32 %0, %1;" : "=r"(u) : "f"(x));
    return u;
}
__device__ __forceinline__ float tf32r(float x) {       // round-to-tf32, keep as float
    return __uint_as_float(tf32_of(x));
}
// D(16x8) += A(16x8,row) * B(8x8,col) ; tf32 inputs, fp32 accumulate
__device__ __forceinline__ void mma16n8k8(float* d,
    unsigned a0, unsigned a1, unsigned a2, unsigned a3,
    unsigned b0, unsigned b1)
{
    asm volatile(
        "mma.sync.aligned.m16n8k8.row.col.f32.tf32.tf32.f32 "
        "{%0,%1,%2,%3}, {%4,%5,%6,%7}, {%8,%9}, {%0,%1,%2,%3};"
        : "+f"(d[0]), "+f"(d[1]), "+f"(d[2]), "+f"(d[3])
        : "r"(a0), "r"(a1), "r"(a2), "r"(a3), "r"(b0), "r"(b1));
}
__device__ __forceinline__ float4 warp_prod_scan4(float4 a) {
    const int lane = threadIdx.x & 31;
    #pragma unroll
    for (int off = 1; off < 32; off <<= 1) {
        float x0 = __shfl_up_sync(0xffffffffu, a.x, off);
        float x1 = __shfl_up_sync(0xffffffffu, a.y, off);
        float x2 = __shfl_up_sync(0xffffffffu, a.z, off);
        float x3 = __shfl_up_sync(0xffffffffu, a.w, off);
        if (lane >= off) { a.x *= x0; a.y *= x1; a.z *= x2; a.w *= x3; }
    }
    return a;
}
__device__ __forceinline__ float4 shfl_up1_or_one4(float4 a) {
    const int lane = threadIdx.x & 31;
    float4 r;
    r.x = __shfl_up_sync(0xffffffffu, a.x, 1);
    r.y = __shfl_up_sync(0xffffffffu, a.y, 1);
    r.z = __shfl_up_sync(0xffffffffu, a.z, 1);
    r.w = __shfl_up_sync(0xffffffffu, a.w, 1);
    if (lane == 0) r = make_float4(1.f, 1.f, 1.f, 1.f);
    return r;
}
__device__ __forceinline__ float4 shfl31_4(float4 a) {
    float4 r;
    r.x = __shfl_sync(0xffffffffu, a.x, 31);
    r.y = __shfl_sync(0xffffffffu, a.y, 31);
    r.z = __shfl_sync(0xffffffffu, a.z, 31);
    r.w = __shfl_sync(0xffffffffu, a.w, 31);
    return r;
}
__device__ __forceinline__ float4 fmax4(float4 a, float e) {
    return make_float4(fmaxf(a.x, e), fmaxf(a.y, e), fmaxf(a.z, e), fmaxf(a.w, e));
}

// ================= kernel A: scan + P + dS + O_intra (3-buffer, 4 blocks/SM) ==
// Mid-chunk normalization m = prod(rows 0..31), q_full = prod(rows 32..63).
//  khT[k][t] = k*m/incl;  rhT[k][t] = r~/m;  rt(global) = r~  (tf32-rounded)
//  P[i][j] = sum_k rh[k][i] khT[k][j] (j<i), diag (j==i), 0
//  dS[k][v] = q_full[k] * sum_t khT[k][t] v[t][v] ; O_intra = P.v -> out
// Buffer lifetimes:  A: w -> khT ;  B: r -> rhT -> PT ;  C: k -> v
// diag accumulated via smem atomicAdd (no dp buffer -> 55.8 KB -> 4 blocks/SM)
struct KASmem {
    union { float w[Cc][PAD]; float khT[Kk][PAD]; } A;
    union { float r[Cc][PAD]; float rhT[Kk][PAD]; float PT[Cc][PAD]; } B;
    union { float k[Cc][PAD]; float v[Cc][PAD]; } C;
    float diag[Cc];
    float sK[Kk];       // q_full per k-column
};

__global__ __launch_bounds__(256, 4) void kA_chunk(
    const float* __restrict__ r, const float* __restrict__ k,
    const float* __restrict__ v, const float* __restrict__ w,
    const float* __restrict__ u, float* __restrict__ out)
{
    extern __shared__ char smem_raw[];
    KASmem& sm = *reinterpret_cast<KASmem*>(smem_raw);

    const int bh = blockIdx.y;
    const int h  = bh & (Hh - 1);
    const int tid  = threadIdx.x;
    const int lane = tid & 31;
    const int wi   = tid >> 5;
    const int g  = lane >> 2;      // mma groupID
    const int tg = lane & 3;       // mma thread-in-group
    const int mw = (wi & 3) * 16;  // warp output row base
    const int nw = (wi >> 2) * 32; // warp output col base

    #pragma unroll 1
    for (int half = 0; half < 2; half++) {
        const int c  = blockIdx.x + half * (NCk / 2);
        const int t0 = c * Cc;

        // ---- stage w, r, k (NOT v) row-major via cp.async; zero diag ----
        if (tid < Cc) sm.diag[tid] = 0.0f;
        {
            const float4* wp = (const float4*)(w + ((size_t)h  * Tt + t0) * Kk);
            const float4* rp = (const float4*)(r + ((size_t)bh * Tt + t0) * Kk);
            const float4* kp = (const float4*)(k + ((size_t)bh * Tt + t0) * Kk);
            #pragma unroll
            for (int i = tid; i < Cc * Kk / 4; i += 256) {
                int t = i >> 4, k0 = (i & 15) * 4;
                cp_async16(&sm.A.w[t][k0], &wp[i]);
                cp_async16(&sm.B.r[t][k0], &rp[i]);
                cp_async16(&sm.C.k[t][k0], &kp[i]);
            }
            cp_async_wait_all();
        }
        __syncthreads();

        // ---- scan phase: read rows into regs, compute all normalized forms ----
        float4 kh0[2], kh1[2], rh0[2], rh1[2];
        {
            float dA = 0.0f, dB = 0.0f;
            #pragma unroll
            for (int gg = 0; gg < 2; gg++) {
                const int kk4 = wi * 8 + gg * 4;
                float4 w0 = fmax4(*(const float4*)&sm.A.w[lane][kk4],      1e-6f);
                float4 w1 = fmax4(*(const float4*)&sm.A.w[32 + lane][kk4], 1e-6f);
                float4 r0 = *(const float4*)&sm.B.r[lane][kk4];
                float4 r1 = *(const float4*)&sm.B.r[32 + lane][kk4];
                float4 c0 = *(const float4*)&sm.C.k[lane][kk4];
                float4 c1 = *(const float4*)&sm.C.k[32 + lane][kk4];

                float4 p = warp_prod_scan4(w0);     // prod rows 0..lane
                float4 q = warp_prod_scan4(w1);     // prod rows 32..32+lane
                float4 m    = shfl31_4(p);          // prod rows 0..31
                float4 qf   = shfl31_4(q);          // prod rows 32..63
                float4 pre  = shfl_up1_or_one4(p);
                float4 pre2 = shfl_up1_or_one4(q);
                float4 u4 = *(const float4*)&u[h * Kk + kk4];

                dA = fmaf(r0.x * c0.x, u4.x, dA); dA = fmaf(r0.y * c0.y, u4.y, dA);
                dA = fmaf(r0.z * c0.z, u4.z, dA); dA = fmaf(r0.w * c0.w, u4.w, dA);
                dB = fmaf(r1.x * c1.x, u4.x, dB); dB = fmaf(r1.y * c1.y, u4.y, dB);
                dB = fmaf(r1.z * c1.z, u4.z, dB); dB = fmaf(r1.w * c1.w, u4.w, dB);

                // normalized forms (pre-rounded to tf32)
                kh0[gg] = make_float4(tf32r(c0.x * m.x / p.x), tf32r(c0.y * m.y / p.y),
                                      tf32r(c0.z * m.z / p.z), tf32r(c0.w * m.w / p.w));
                kh1[gg] = make_float4(tf32r(c1.x / q.x), tf32r(c1.y / q.y),
                                      tf32r(c1.z / q.z), tf32r(c1.w / q.w));
                rh0[gg] = make_float4(tf32r(r0.x * pre.x / m.x), tf32r(r0.y * pre.y / m.y),
                                      tf32r(r0.z * pre.z / m.z), tf32r(r0.w * pre.w / m.w));
                rh1[gg] = make_float4(tf32r(r1.x * pre2.x), tf32r(r1.y * pre2.y),
                                      tf32r(r1.z * pre2.z), tf32r(r1.w * pre2.w));

                // r~ to global (transposed [k][t], tf32-rounded), coalesced per kk
                {
                    float* rtb = g_rt + ((size_t)(bh * NCk + c)) * Kk * Cc;
                    float rt0v[4] = {tf32r(r0.x * pre.x), tf32r(r0.y * pre.y),
                                     tf32r(r0.z * pre.z), tf32r(r0.w * pre.w)};
                    float rt1v[4] = {tf32r(r1.x * (m.x * pre2.x)), tf32r(r1.y * (m.y * pre2.y)),
                                     tf32r(r1.z * (m.z * pre2.z)), tf32r(r1.w * (m.w * pre2.w))};
                    #pragma unroll
                    for (int cc = 0; cc < 4; cc++) {
                        rtb[(kk4 + cc) * Cc + lane]      = rt0v[cc];
                        rtb[(kk4 + cc) * Cc + 32 + lane] = rt1v[cc];
                    }
                }
                if (lane == 0) {
                    float4 aC;
                    aC.x = m.x * qf.x; aC.y = m.y * qf.y;
                    aC.z = m.z * qf.z; aC.w = m.w * qf.w;
                    *(float4*)&g_aC[(bh * NCk + c) * Kk + kk4] = aC;
                    *(float4*)&sm.sK[kk4] = qf;
                }
            }
            // diag accumulation via smem atomics (replaces dp buffer)
            atomicAdd(&sm.diag[lane],      dA);
            atomicAdd(&sm.diag[32 + lane], dB);
        }
        __syncthreads();   // sync1: all w/r/k reads + diag atomics complete

        // ---- overlap: v load into C (k dead) + transposed writes ----
        {
            const float4* vp = (const float4*)(v + ((size_t)bh * Tt + t0) * Vv);
            #pragma unroll
            for (int i = tid; i < Cc * Kk / 4; i += 256) {
                int t = i >> 4, k0 = (i & 15) * 4;
                cp_async16(&sm.C.v[t][k0], &vp[i]);
            }
        }
        #pragma unroll
        for (int gg = 0; gg < 2; gg++) {
            const int kk4 = wi * 8 + gg * 4;
            sm.A.khT[kk4 + 0][lane] = kh0[gg].x; sm.A.khT[kk4 + 1][lane] = kh0[gg].y;
            sm.A.khT[kk4 + 2][lane] = kh0[gg].z; sm.A.khT[kk4 + 3][lane] = kh0[gg].w;
            sm.A.khT[kk4 + 0][32 + lane] = kh1[gg].x; sm.A.khT[kk4 + 1][32 + lane] = kh1[gg].y;
            sm.A.khT[kk4 + 2][32 + lane] = kh1[gg].z; sm.A.khT[kk4 + 3][32 + lane] = kh1[gg].w;
            sm.B.rhT[kk4 + 0][lane] = rh0[gg].x; sm.B.rhT[kk4 + 1][lane] = rh0[gg].y;
            sm.B.rhT[kk4 + 2][lane] = rh0[gg].z; sm.B.rhT[kk4 + 3][lane] = rh0[gg].w;
            sm.B.rhT[kk4 + 0][32 + lane] = rh1[gg].x; sm.B.rhT[kk4 + 1][32 + lane] = rh1[gg].y;
            sm.B.rhT[kk4 + 2][32 + lane] = rh1[gg].z; sm.B.rhT[kk4 + 3][32 + lane] = rh1[gg].w;
        }
        __syncthreads();   // sync2: khT, rhT, diag visible

        float acc[4][4];

        // ---- P MMA: P[i][j] = sum_k rhT[k][i] khT[k][j]  (no v needed) ----
        #pragma unroll
        for (int nt = 0; nt < 4; nt++)
            #pragma unroll
            for (int q2 = 0; q2 < 4; q2++) acc[nt][q2] = 0.0f;
        #pragma unroll
        for (int ks = 0; ks < 8; ks++) {
            const int kd0 = ks * 8 + tg;
            const int kd1 = kd0 + 4;
            unsigned a0 = __float_as_uint(sm.B.rhT[kd0][mw + g]);
            unsigned a1 = __float_as_uint(sm.B.rhT[kd0][mw + g + 8]);
            unsigned a2 = __float_as_uint(sm.B.rhT[kd1][mw + g]);
            unsigned a3 = __float_as_uint(sm.B.rhT[kd1][mw + g + 8]);
            #pragma unroll
            for (int nt = 0; nt < 4; nt++) {
                unsigned b0 = __float_as_uint(sm.A.khT[kd0][nw + nt * 8 + g]);
                unsigned b1 = __float_as_uint(sm.A.khT[kd1][nw + nt * 8 + g]);
                mma16n8k8(acc[nt], a0, a1, a2, a3, b0, b1);
            }
        }
        float dg0 = sm.diag[mw + g];
        float dg1 = sm.diag[mw + g + 8];

        cp_async_wait_all();   // v arrived (this thread's group)
        __syncthreads();       // sync3: P-MMA rhT reads done; v visible block-wide

        // ---- store masked PT -> B (rhT dead) ----
        #pragma unroll
        for (int nt = 0; nt < 4; nt++) {
            int jb = nw + nt * 8 + 2 * tg;
            int i0 = mw + g, i1 = mw + g + 8;
            sm.B.PT[jb][i0]     = tf32r((jb     < i0) ? acc[nt][0] : ((jb     == i0) ? dg0 : 0.0f));
            sm.B.PT[jb + 1][i0] = tf32r((jb + 1 < i0) ? acc[nt][1] : ((jb + 1 == i0) ? dg0 : 0.0f));
            sm.B.PT[jb][i1]     = tf32r((jb     < i1) ? acc[nt][2] : ((jb     == i1) ? dg1 : 0.0f));
            sm.B.PT[jb + 1][i1] = tf32r((jb + 1 < i1) ? acc[nt][3] : ((jb + 1 == i1) ? dg1 : 0.0f));
        }

        // ---- dS MMA: dS[k][v] = sK[k] * sum_t khT[k][t] v[t][v] ----
        #pragma unroll
        for (int nt = 0; nt < 4; nt++)
            #pragma unroll
            for (int q2 = 0; q2 < 4; q2++) acc[nt][q2] = 0.0f;
        #pragma unroll
        for (int ks = 0; ks < 8; ks++) {
            const int td0 = ks * 8 + tg;
            const int td1 = td0 + 4;
            unsigned a0 = __float_as_uint(sm.A.khT[mw + g][td0]);
            unsigned a1 = __float_as_uint(sm.A.khT[mw + g + 8][td0]);
            unsigned a2 = __float_as_uint(sm.A.khT[mw + g][td1]);
            unsigned a3 = __float_as_uint(sm.A.khT[mw + g + 8][td1]);
            #pragma unroll
            for (int nt = 0; nt < 4; nt++) {
                unsigned b0 = tf32_of(sm.C.v[td0][nw + nt * 8 + g]);
                unsigned b1 = tf32_of(sm.C.v[td1][nw + nt * 8 + g]);
                mma16n8k8(acc[nt], a0, a1, a2, a3, b0, b1);
            }
        }
        {
            float s0 = sm.sK[mw + g], s1 = sm.sK[mw + g + 8];
            float* dsp = g_dS + (size_t)(bh * NCk + c) * Kk * Vv;
            #pragma unroll
            for (int nt = 0; nt < 4; nt++) {
                int col = nw + nt * 8 + 2 * tg;
                *(float2*)&dsp[(size_t)(mw + g)     * Vv + col] =
                    make_float2(acc[nt][0] * s0, acc[nt][1] * s0);
                *(float2*)&dsp[(size_t)(mw + g + 8) * Vv + col] =
                    make_float2(acc[nt][2] * s1, acc[nt][3] * s1);
            }
        }
        __syncthreads();   // sync4: PT visible

        // ---- O_intra MMA: O[t][v] = sum_j PT[j][t] v[j][v]  -> out ----
        #pragma unroll
        for (int nt = 0; nt < 4; nt++)
            #pragma unroll
            for (int q2 = 0; q2 < 4; q2++) acc[nt][q2] = 0.0f;
        #pragma unroll
        for (int ks = 0; ks < 8; ks++) {
            const int jd0 = ks * 8 + tg;
            const int jd1 = jd0 + 4;
            unsigned a0 = __float_as_uint(sm.B.PT[jd0][mw + g]);
            unsigned a1 = __float_as_uint(sm.B.PT[jd0][mw + g + 8]);
            unsigned a2 = __float_as_uint(sm.B.PT[jd1][mw + g]);
            unsigned a3 = __float_as_uint(sm.B.PT[jd1][mw + g + 8]);
            #pragma unroll
            for (int nt = 0; nt < 4; nt++) {
                unsigned b0 = tf32_of(sm.C.v[jd0][nw + nt * 8 + g]);
                unsigned b1 = tf32_of(sm.C.v[jd1][nw + nt * 8 + g]);
                mma16n8k8(acc[nt], a0, a1, a2, a3, b0, b1);
            }
        }
        {
            float* op = out + ((size_t)bh * Tt + t0) * Vv;
            #pragma unroll
            for (int nt = 0; nt < 4; nt++) {
                int col = nw + nt * 8 + 2 * tg;
                *(float2*)&op[(size_t)(mw + g)     * Vv + col] = make_float2(acc[nt][0], acc[nt][1]);
                *(float2*)&op[(size_t)(mw + g + 8) * Vv + col] = make_float2(acc[nt][2], acc[nt][3]);
            }
        }
        __syncthreads();   // before restaging next chunk
    }
}

// ================= kernel 2: sequential chunk-level state scan =================
__global__ __launch_bounds__(256) void k2_scan(
    const float* __restrict__ state_in, float* __restrict__ out)
{
    const int bh  = blockIdx.y;
    const int tid = threadIdx.x;
    const int fi  = blockIdx.x * 256 + tid;
    const int krow = fi >> 4;

    float4 S = ((const float4*)(state_in + (size_t)bh * Kk * Vv))[fi];

    const float*  aCb = g_aC + bh * NCk * Kk;
    const float4* dSb = (const float4*)(g_dS + (size_t)bh * NCk * Kk * Vv);
    float4*       Scb = (float4*)(g_Sc + (size_t)bh * NCk * Kk * Vv);

    float4 db[2][4];
    float  ab[2][4];

    #pragma unroll
    for (int j = 0; j < 4; j++) {
        db[0][j] = dSb[(size_t)j * 1024 + fi];
        ab[0][j] = aCb[j * Kk + krow];
    }

    #pragma unroll 1
    for (int gq = 0; gq < NCk / 4; gq++) {
        const int cur = gq & 1;
        if (gq + 1 < NCk / 4) {
            #pragma unroll
            for (int j = 0; j < 4; j++) {
                int c = (gq + 1) * 4 + j;
                db[cur ^ 1][j] = dSb[(size_t)c * 1024 + fi];
                ab[cur ^ 1][j] = aCb[c * Kk + krow];
            }
        }
        #pragma unroll
        for (int j = 0; j < 4; j++) {
            int c = gq * 4 + j;
            Scb[(size_t)c * 1024 + fi] = S;
            float a = ab[cur][j]; float4 d = db[cur][j];
            S.x = fmaf(a, S.x, d.x); S.y = fmaf(a, S.y, d.y);
            S.z = fmaf(a, S.z, d.z); S.w = fmaf(a, S.w, d.w);
        }
    }

    ((float4*)(out + (size_t)OUT_T_SIZE + (size_t)bh * Kk * Vv))[fi] = S;
}

// ================= kernel B: cross-chunk term, O += rt . S =================
// One chunk per block (grid 1024): 6 blocks/SM of overlap hides staging latency.
struct KBSmem {
    float rtT[Kk][PAD];   // [k][t], tf32-rounded already
    float S[Kk][PAD];     // [k][v], raw fp32 (converted at fragment load)
};

__global__ __launch_bounds__(256, 6) void kB_cross(
    float* __restrict__ out)
{
    extern __shared__ char smem_raw[];
    KBSmem& sm = *reinterpret_cast<KBSmem*>(smem_raw);

    const int c  = blockIdx.x;
    const int bh = blockIdx.y;
    const int t0 = c * Cc;
    const int tid  = threadIdx.x;
    const int lane = tid & 31;
    const int wi   = tid >> 5;
    const int g  = lane >> 2;
    const int tg = lane & 3;
    const int mw = (wi & 3) * 16;
    const int nw = (wi >> 2) * 32;

    // ---- stage rtT + Sc ----
    {
        const float4* rp = (const float4*)(g_rt + ((size_t)(bh * NCk + c)) * Kk * Cc);
        const float4* Sp = (const float4*)(g_Sc + (size_t)(bh * NCk + c) * Kk * Vv);
        #pragma unroll
        for (int i = tid; i < Kk * Cc / 4; i += 256) {
            int row = i >> 4, c4 = (i & 15) * 4;
            cp_async16(&sm.rtT[row][c4], &rp[i]);
            cp_async16(&sm.S[row][c4],   &Sp[i]);
        }
        cp_async_wait_all();
    }
    __syncthreads();

    // ---- O_cross MMA: O[t][v] += sum_k rtT[k][t] S[k][v] ----
    float acc[4][4];
    #pragma unroll
    for (int nt = 0; nt < 4; nt++)
        #pragma unroll
        for (int q2 = 0; q2 < 4; q2++) acc[nt][q2] = 0.0f;

    #pragma unroll
    for (int ks = 0; ks < 8; ks++) {
        const int kd0 = ks * 8 + tg;
        const int kd1 = kd0 + 4;
        unsigned a0 = __float_as_uint(sm.rtT[kd0][mw + g]);
        unsigned a1 = __float_as_uint(sm.rtT[kd0][mw + g + 8]);
        unsigned a2 = __float_as_uint(sm.rtT[kd1][mw + g]);
        unsigned a3 = __float_as_uint(sm.rtT[kd1][mw + g + 8]);
        #pragma unroll
        for (int nt = 0; nt < 4; nt++) {
            unsigned b0 = tf32_of(sm.S[kd0][nw + nt * 8 + g]);
            unsigned b1 = tf32_of(sm.S[kd1][nw + nt * 8 + g]);
            mma16n8k8(acc[nt], a0, a1, a2, a3, b0, b1);
        }
    }

    // ---- read-modify-write out ----
    float* op = out + ((size_t)bh * Tt + t0) * Vv;
    #pragma unroll
    for (int nt = 0; nt < 4; nt++) {
        int col = nw + nt * 8 + 2 * tg;
        float2* p0 = (float2*)&op[(size_t)(mw + g)     * Vv + col];
        float2* p1 = (float2*)&op[(size_t)(mw + g + 8) * Vv + col];
        float2 o0 = *p0, o1 = *p1;
        o0.x += acc[nt][0]; o0.y += acc[nt][1];
        o1.x += acc[nt][2]; o1.y += acc[nt][3];
        *p0 = o0; *p1 = o1;
    }
}

// ---------------- launch ----------------
extern "C" void kernel_launch(void* const* d_in, const int* in_sizes, int n_in,
                              void* d_out, int out_size)
{
    const float* r  = (const float*)d_in[0];
    const float* k  = (const float*)d_in[1];
    const float* v  = (const float*)d_in[2];
    const float* w  = (const float*)d_in[3];
    const float* u  = (const float*)d_in[4];
    const float* st = (const float*)d_in[5];
    float* out = (float*)d_out;

    static bool configured = false;
    if (!configured) {
        cudaFuncSetAttribute(kA_chunk, cudaFuncAttributeMaxDynamicSharedMemorySize,
                             (int)sizeof(KASmem));
        cudaFuncSetAttribute(kB_cross, cudaFuncAttributeMaxDynamicSharedMemorySize,
                             (int)sizeof(KBSmem));
        configured = true;
    }

    kA_chunk<<<dim3(NCk / 2, BH), 256, sizeof(KASmem)>>>(r, k, v, w, u, out);
    k2_scan<<<dim3(4, BH), 256>>>(st, out);
    kB_cross<<<dim3(NCk, BH), 256, sizeof(KBSmem)>>>(out);
}